// round 8
// baseline (speedup 1.0000x reference)
#include <cuda_runtime.h>
#include <math_constants.h>

// SoftmaxTreeWithLoss on GB300 (sm_103a).
// x: [N=16, C=4096, H=26, W=26] f32; label: [N,26,26] i32 in [0,C)
// Tree: group 0 = channels [0,512) (roots); then 512 groups of 7 children.
//
// loss_pos = -( sum of self-contained child-group logps
//               + x[root_node] - LSE(root group) )
//
// R7: 64 positions/CTA with float2 loads (256B per warp-load) + explicit
// double-buffered 8-load batches so >=8 independent loads stay in flight per
// streaming warp (R6 measured only ~2). 8 streaming warps (64 root channels
// each) + 2 chain-walk warps, all overlapped. 10816 = 169 * 64 exactly.

#define HW_SZ 676              // 26*26
#define HC2   338              // HW_SZ/2, channel stride in float2
#define CN 4096
#define POS_PER_BLOCK 64
#define NW_STREAM 8
#define CH_PER_WARP 64         // 512 / 8
#define BATCH 8
#define THREADS 320            // 8 streaming + 2 chain warps

__global__ __launch_bounds__(THREADS, 3)
void tree_loss_kernel(const float* __restrict__ x,
                      const int*   __restrict__ label,
                      const int*   __restrict__ group_offsets,
                      const int*   __restrict__ group_sizes,
                      const int*   __restrict__ cid_groups,
                      const int*   __restrict__ parents,
                      float* __restrict__ out,
                      int M, float inv_norm)
{
    __shared__ float sm_s[NW_STREAM][POS_PER_BLOCK];

    const int lane = threadIdx.x & 31;
    const int w    = threadIdx.x >> 5;

    if (w < NW_STREAM) {
        // ---- streaming warps: lane owns position pair (2*lane, 2*lane+1) ----
        const int p0 = blockIdx.x * POS_PER_BLOCK + 2 * lane;
        const bool valid = p0 < M;           // M even => p0+1 also valid
        const int n  = valid ? (p0 / HW_SZ) : 0;
        const int hw = valid ? (p0 - n * HW_SZ) : 0;
        // hw is even (pos parity == hw parity, pairs never straddle n)
        const float2* base2 =
            (const float2*)(x + (size_t)n * (CN * HW_SZ) + hw);
        const int c0 = w * CH_PER_WARP;

        float ax0 = 0.f, ay0 = 0.f, ax1 = 0.f, ay1 = 0.f;
        if (valid) {
            float2 va[BATCH], vb[BATCH];
            #pragma unroll
            for (int j = 0; j < BATCH; j++)
                va[j] = base2[(size_t)(c0 + j) * HC2];

            #pragma unroll
            for (int b = 0; b < CH_PER_WARP / BATCH; b++) {
                float2* cur = (b & 1) ? vb : va;
                float2* nxt = (b & 1) ? va : vb;
                if (b < CH_PER_WARP / BATCH - 1) {
                    #pragma unroll
                    for (int j = 0; j < BATCH; j++)
                        nxt[j] = base2[(size_t)(c0 + (b + 1) * BATCH + j) * HC2];
                }
                #pragma unroll
                for (int j = 0; j < BATCH; j += 2) {
                    ax0 += __expf(cur[j].x);
                    ay0 += __expf(cur[j].y);
                    ax1 += __expf(cur[j + 1].x);
                    ay1 += __expf(cur[j + 1].y);
                }
            }
        }
        sm_s[w][2 * lane]     = ax0 + ax1;
        sm_s[w][2 * lane + 1] = ay0 + ay1;

        __syncthreads();
    } else {
        // ---- chain warps (w=8,9): walk parent chain for 32 positions each ----
        const int li  = (w - NW_STREAM) * 32 + lane;       // 0..63 in block
        const int pos = blockIdx.x * POS_PER_BLOCK + li;
        const bool valid = pos < M;
        const int n  = valid ? (pos / HW_SZ) : 0;
        const int hw = valid ? (pos - n * HW_SZ) : 0;
        const float* base = x + (size_t)n * (CN * HW_SZ) + hw;

        float child_lp   = 0.f;   // self-contained child-group log-probs
        float root_logit = 0.f;   // group-0 logits on the chain
        float root_cnt   = 0.f;   // # group-0 terms (each needs lse0)

        int cur = valid ? label[pos] : -1;
        #pragma unroll 1
        for (int d = 0; d < 8; d++) {          // MAX_DEPTH = 8
            if (!__ballot_sync(0xffffffffu, cur >= 0)) break;
            if (cur >= 0) {
                const int g = cid_groups[cur];
                if (g == 0) {
                    root_logit += base[cur * HW_SZ];
                    root_cnt   += 1.f;
                } else {
                    const int go = group_offsets[g];
                    const int gs = group_sizes[g];     // 7
                    float ss = 0.f, xv = 0.f;
                    for (int j = 0; j < gs; j++) {
                        const float v = base[(go + j) * HW_SZ];
                        ss += __expf(v);
                        if (go + j == cur) xv = v;
                    }
                    child_lp += xv - __logf(ss);
                }
                cur = parents[cur];
            }
        }

        __syncthreads();

        // merge the 8 streaming partials for this position
        float S = 0.f;
        #pragma unroll
        for (int q = 0; q < NW_STREAM; q++) S += sm_s[q][li];

        float loss = 0.f;
        if (valid)
            loss = -(child_lp + root_logit - root_cnt * __logf(S));

        #pragma unroll
        for (int o = 16; o; o >>= 1)
            loss += __shfl_xor_sync(0xffffffffu, loss, o);
        if (lane == 0)
            atomicAdd(out, loss * inv_norm);
    }
}

extern "C" void kernel_launch(void* const* d_in, const int* in_sizes, int n_in,
                              void* d_out, int out_size)
{
    const float* x     = (const float*)d_in[0];
    const int* label   = (const int*)d_in[1];
    const int* g_off   = (const int*)d_in[2];
    const int* g_sz    = (const int*)d_in[3];
    const int* cid     = (const int*)d_in[4];
    const int* par     = (const int*)d_in[5];
    float* out         = (float*)d_out;

    const int M = in_sizes[1];          // N*H*W (label element count)
    const int N = M / HW_SZ;            // batch size for normalization
    const float inv_norm = 1.0f / (float)N;

    cudaMemsetAsync(d_out, 0, sizeof(float));

    const int blocks = (M + POS_PER_BLOCK - 1) / POS_PER_BLOCK;
    tree_loss_kernel<<<blocks, THREADS>>>(x, label, g_off, g_sz, cid, par,
                                          out, M, inv_norm);
}